// round 15
// baseline (speedup 1.0000x reference)
#include <cuda_runtime.h>
#include <cuda_bf16.h>
#include <math.h>
#include <stdint.h>

// ---------------- problem dims ----------------
#define Bt   8
#define Sq   1024
#define Dm   1024
#define NH   16
#define HD1  64
#define NE   8
#define NHM  8
#define HDM  128
#define CAP  320
#define NT   (Bt*Sq)
#define NTD  ((size_t)NT*Dm)
#define EROWS (Bt*CAP)
#define EINSZ ((size_t)NE*Bt*CAP*Dm)
#define DMDM ((size_t)Dm*Dm)

// ---------------- scratch ----------------
static __device__ float g_attn[NTD];
static __device__ float g_x1[NTD];

static __device__ __nv_bfloat16 g_xh[NTD];
static __device__ __nv_bfloat16 g_qkvh[3*NTD];
static __device__ __nv_bfloat16 g_oh[NTD];
static __device__ __nv_bfloat16 g_einh[EINSZ];
static __device__ __nv_bfloat16 g_eqkv[3*EINSZ];
static __device__ __nv_bfloat16 g_eoh[EINSZ];
static __device__ __nv_bfloat16 g_eoutb[EINSZ];
static __device__ __nv_bfloat16 g_wqkvh[3*DMDM];
static __device__ __nv_bfloat16 g_woh[DMDM];
static __device__ __nv_bfloat16 g_ewh[3*NE*DMDM];
static __device__ __nv_bfloat16 g_ewoh[NE*DMDM];
static __device__ float g_bqkv[3*Dm];

static __device__ int   g_i0[NT], g_i1[NT];
static __device__ float g_g0[NT], g_g1[NT];
static __device__ int   g_p0[NT], g_p1[NT];
static __device__ int   g_k0[NT], g_k1[NT];

static __device__ float g_Psum[NE];
static __device__ float g_fcnt[NE];
static __device__ float g_zsum;

// ---------------- PTX helpers ----------------
__device__ __forceinline__ uint32_t smem_u32(const void* p) {
    uint32_t a;
    asm("{ .reg .u64 t; cvta.to.shared.u64 t, %1; cvt.u32.u64 %0, t; }" : "=r"(a) : "l"(p));
    return a;
}
__device__ __forceinline__ void cp16(uint32_t dst, const void* src) {
    asm volatile("cp.async.cg.shared.global [%0], [%1], 16;" :: "r"(dst), "l"(src));
}
__device__ __forceinline__ void ldmA(uint32_t* a, uint32_t addr) {
    asm volatile("ldmatrix.sync.aligned.m8n8.x4.shared.b16 {%0,%1,%2,%3}, [%4];"
        : "=r"(a[0]), "=r"(a[1]), "=r"(a[2]), "=r"(a[3]) : "r"(addr));
}
__device__ __forceinline__ void ldmT(uint32_t* a, uint32_t addr) {
    asm volatile("ldmatrix.sync.aligned.m8n8.x4.trans.shared.b16 {%0,%1,%2,%3}, [%4];"
        : "=r"(a[0]), "=r"(a[1]), "=r"(a[2]), "=r"(a[3]) : "r"(addr));
}
__device__ __forceinline__ void mma_bf16(float* d, const uint32_t* a, const uint32_t* b) {
    asm volatile(
        "mma.sync.aligned.m16n8k16.row.col.f32.bf16.bf16.f32 "
        "{%0,%1,%2,%3}, {%4,%5,%6,%7}, {%8,%9}, {%0,%1,%2,%3};"
        : "+f"(d[0]), "+f"(d[1]), "+f"(d[2]), "+f"(d[3])
        : "r"(a[0]), "r"(a[1]), "r"(a[2]), "r"(a[3]), "r"(b[0]), "r"(b[1]));
}
__device__ __forceinline__ uint32_t packbf(float a, float b) {
    __nv_bfloat162 v = __float22bfloat162_rn(make_float2(a, b));
    return *(uint32_t*)&v;
}

// ---------------- GEMM via mma.sync (bf16, BM=256, BK=64, B natural [K,N]) --
// CTA tile 256x128, 512 threads (16 warps: 8m x 2n, warp tile 32x64).
#define BK 64
#define ROWA 144
#define ROWBB 272
#define ASTG (256*ROWA)        // 36864
#define BSTG (64*ROWBB)        // 17408
#define STG2 (ASTG+BSTG)       // 54272
#define NSTG 3
#define GEMM_SMEM (NSTG*STG2)  // 162816

template <int OUTBF>
__global__ __launch_bounds__(512, 1) void gemm_mma_kernel(
    const __nv_bfloat16* __restrict__ A, const __nv_bfloat16* __restrict__ W,
    const float* __restrict__ bias, void* __restrict__ Cv,
    int M, int N, int K, size_t sA, size_t sB, size_t sC, size_t sbias, int zmod)
{
    extern __shared__ char sm_[];
    uint32_t smb = smem_u32(sm_);

    int t = threadIdx.x, lane = t & 31, wid = t >> 5;
    int n0 = blockIdx.x * 128, m0 = blockIdx.y * 256;
    int z = blockIdx.z;
    A += (size_t)(z % zmod) * sA;
    W += (size_t)z * sB;
    if (bias) bias += (size_t)z * sbias;

    int wm = (wid & 7) * 32;
    int wn = (wid >> 3) * 64;
    const int NC = K / BK;

    float acc[2][8][4];
#pragma unroll
    for (int i = 0; i < 2; i++)
#pragma unroll
        for (int j = 0; j < 8; j++)
#pragma unroll
            for (int q = 0; q < 4; q++) acc[i][j][q] = 0.f;

    // A cp.async: 256 rows x 8 chunks = 2048 cp16; 512 thr -> 4 each (64-row groups)
    int rb = t >> 3, c8 = t & 7;
    const __nv_bfloat16* Ap = A + (size_t)(m0 + rb) * K + c8 * 8;
    uint32_t waA = (uint32_t)rb * ROWA + c8 * 16;
    const size_t rstepA = (size_t)64 * K;
    // B cp.async: 64 k-rows x 16 chunks = 1024 cp16; 512 thr -> 2 each (32-row groups)
    int rB = t >> 4, cB = t & 15;
    const __nv_bfloat16* Wp = W + (size_t)rB * N + n0 + cB * 8;
    uint32_t waB = (uint32_t)rB * ROWBB + cB * 16;
    const size_t rstepB = (size_t)32 * N;

#pragma unroll
    for (int s = 0; s < 2; s++) {
        uint32_t stg = smb + s * STG2;
        int kc = s * BK;
#pragma unroll
        for (int j = 0; j < 4; j++)
            cp16(stg + waA + j * (64 * ROWA), Ap + kc + j * rstepA);
#pragma unroll
        for (int j = 0; j < 2; j++)
            cp16(stg + ASTG + waB + j * (32 * ROWBB), Wp + (size_t)kc * N + j * rstepB);
        asm volatile("cp.async.commit_group;");
    }

    uint32_t a_row = (uint32_t)(wm + (lane & 15)) * ROWA + (lane >> 4) * 16;
    uint32_t b_col = (uint32_t)(lane & 15) * ROWBB + wn * 2 + (lane >> 4) * 16;

    int sidx = 0;
    for (int c = 0; c < NC; c++) {
        asm volatile("cp.async.wait_group 1;");
        __syncthreads();
        if (c + 2 < NC) {
            int sn = sidx + 2; if (sn >= NSTG) sn -= NSTG;
            uint32_t stg = smb + sn * STG2;
            int kc = (c + 2) * BK;
#pragma unroll
            for (int j = 0; j < 4; j++)
                cp16(stg + waA + j * (64 * ROWA), Ap + kc + j * rstepA);
#pragma unroll
            for (int j = 0; j < 2; j++)
                cp16(stg + ASTG + waB + j * (32 * ROWBB), Wp + (size_t)kc * N + j * rstepB);
        }
        asm volatile("cp.async.commit_group;");

        uint32_t ab = smb + sidx * STG2;
        uint32_t bb = ab + ASTG;

#pragma unroll
        for (int ks = 0; ks < 4; ks++) {
            uint32_t afr[2][4];
#pragma unroll
            for (int mt = 0; mt < 2; mt++)
                ldmA(afr[mt], ab + a_row + mt * (16 * ROWA) + ks * 32);

            uint32_t bfr[8][2];
#pragma unroll
            for (int nb = 0; nb < 4; nb++) {
                uint32_t q[4];
                ldmT(q, bb + b_col + ks * (16 * ROWBB) + nb * 32);
                bfr[nb * 2][0]     = q[0]; bfr[nb * 2][1]     = q[1];
                bfr[nb * 2 + 1][0] = q[2]; bfr[nb * 2 + 1][1] = q[3];
            }
#pragma unroll
            for (int mt = 0; mt < 2; mt++)
#pragma unroll
                for (int nt = 0; nt < 8; nt++)
                    mma_bf16(acc[mt][nt], afr[mt], bfr[nt]);
        }
        if (++sidx == NSTG) sidx = 0;
    }

#pragma unroll
    for (int mt = 0; mt < 2; mt++) {
        int m = m0 + wm + mt * 16 + (lane >> 2);
#pragma unroll
        for (int nt = 0; nt < 8; nt++) {
            int n = n0 + wn + nt * 8 + (lane & 3) * 2;
            float bv0 = bias ? bias[n] : 0.f;
            float bv1 = bias ? bias[n + 1] : 0.f;
            float v0 = acc[mt][nt][0] + bv0, v1 = acc[mt][nt][1] + bv1;
            float v2 = acc[mt][nt][2] + bv0, v3 = acc[mt][nt][3] + bv1;
            if (OUTBF == 0) {
                float* C = (float*)Cv + (size_t)z * sC;
                *(float2*)&C[(size_t)m * N + n]       = make_float2(v0, v1);
                *(float2*)&C[(size_t)(m + 8) * N + n] = make_float2(v2, v3);
            } else {
                __nv_bfloat16* C = (__nv_bfloat16*)Cv + (size_t)z * sC;
                *(uint32_t*)&C[(size_t)m * N + n]       = packbf(v0, v1);
                *(uint32_t*)&C[(size_t)(m + 8) * N + n] = packbf(v2, v3);
            }
        }
    }
}

// ---------------- expert flash (bf16 mma, HD=128, 2 CTA/SM, Obuf aliased) ---
#define EF_PITCH 272
#define EF_QS 0
#define EF_KV0 17408
#define EF_MS  87040
#define EF_LS  87296
#define EF_AS  87552
#define EF_RM  87808
#define EF_RS  88320
#define EF_SMEM 88832

__global__ __launch_bounds__(256, 2) void eflash_kernel(
    const __nv_bfloat16* __restrict__ Q, const __nv_bfloat16* __restrict__ K,
    const __nv_bfloat16* __restrict__ V, __nv_bfloat16* __restrict__ O,
    float scale)
{
    extern __shared__ char sm_[];
    float* Obuf = (float*)(sm_ + EF_KV0);
    float* m_s  = (float*)(sm_ + EF_MS);
    float* l_s  = (float*)(sm_ + EF_LS);
    float* a_s  = (float*)(sm_ + EF_AS);
    float* redm = (float*)(sm_ + EF_RM);
    float* reds = (float*)(sm_ + EF_RS);
    uint32_t smb = smem_u32(sm_);

    int t = threadIdx.x, lane = t & 31, wid = t >> 5;
    int half = wid >> 2, wm = (wid & 3) * 16, wn2 = half * 32;
    int slice = blockIdx.y;
    int sb = slice >> 3, h = slice & 7;
    size_t base = (size_t)sb * CAP * 1024 + (size_t)h * HDM;
    int q0 = blockIdx.x * 64;

#pragma unroll
    for (int j = 0; j < 4; j++) {
        int id = t + 256 * j;
        int r = id >> 4, c = id & 15;
        *(uint4*)(sm_ + EF_QS + r * EF_PITCH + c * 16) =
            *(const uint4*)(Q + base + (size_t)(q0 + r) * 1024 + c * 8);
    }
    if (t < 64) { m_s[t] = -1e30f; l_s[t] = 0.f; }

    {
#pragma unroll
        for (int j = 0; j < 4; j++) {
            int id = t + 256 * j;
            int rr = id >> 4, cc = id & 15;
            size_t g = base + (size_t)rr * 1024 + cc * 8;
            cp16(smb + EF_KV0 + rr * EF_PITCH + cc * 16, K + g);
            cp16(smb + EF_KV0 + 17408 + rr * EF_PITCH + cc * 16, V + g);
        }
        asm volatile("cp.async.commit_group;");
    }

    float o[16][4];
#pragma unroll
    for (int i = 0; i < 16; i++)
#pragma unroll
        for (int q = 0; q < 4; q++) o[i][q] = 0.f;

    int rl = wm + (lane >> 2), rh = rl + 8;
    int nq = lane >> 2, kr = lane & 3;
    const int NTILE = CAP / 64;

    for (int kt = 0; kt < NTILE; kt++) {
        __syncthreads();
        if (kt + 1 < NTILE) {
            uint32_t stg = smb + EF_KV0 + ((kt + 1) & 1) * 34816;
#pragma unroll
            for (int j = 0; j < 4; j++) {
                int id = t + 256 * j;
                int rr = id >> 4, cc = id & 15;
                size_t g = base + (size_t)((kt + 1) * 64 + rr) * 1024 + cc * 8;
                cp16(stg + rr * EF_PITCH + cc * 16, K + g);
                cp16(stg + 17408 + rr * EF_PITCH + cc * 16, V + g);
            }
        }
        asm volatile("cp.async.commit_group;");
        asm volatile("cp.async.wait_group 1;");
        __syncthreads();

        uint32_t ksb = smb + EF_KV0 + (kt & 1) * 34816;
        uint32_t vsb = ksb + 17408;
        const char* kcp = sm_ + (ksb - smb);

        float s[4][4];
#pragma unroll
        for (int nt = 0; nt < 4; nt++)
#pragma unroll
            for (int q = 0; q < 4; q++) s[nt][q] = 0.f;
#pragma unroll
        for (int ks = 0; ks < 8; ks++) {
            uint32_t af[4];
            ldmA(af, smb + EF_QS + (wm + (lane & 15)) * EF_PITCH + ks * 32 + (lane >> 4) * 16);
#pragma unroll
            for (int nt = 0; nt < 4; nt++) {
                const char* p = kcp + (wn2 + nt * 8 + nq) * EF_PITCH + ks * 32 + kr * 4;
                uint32_t bb[2];
                bb[0] = *(const uint32_t*)p;
                bb[1] = *(const uint32_t*)(p + 16);
                mma_bf16(s[nt], af, bb);
            }
        }

        float mxlo = -1e30f, mxhi = -1e30f;
#pragma unroll
        for (int nt = 0; nt < 4; nt++) {
            s[nt][0] *= scale; s[nt][1] *= scale; s[nt][2] *= scale; s[nt][3] *= scale;
            mxlo = fmaxf(mxlo, fmaxf(s[nt][0], s[nt][1]));
            mxhi = fmaxf(mxhi, fmaxf(s[nt][2], s[nt][3]));
        }
        mxlo = fmaxf(mxlo, __shfl_xor_sync(0xffffffff, mxlo, 1));
        mxlo = fmaxf(mxlo, __shfl_xor_sync(0xffffffff, mxlo, 2));
        mxhi = fmaxf(mxhi, __shfl_xor_sync(0xffffffff, mxhi, 1));
        mxhi = fmaxf(mxhi, __shfl_xor_sync(0xffffffff, mxhi, 2));
        if ((lane & 3) == 0) { redm[half * 64 + rl] = mxlo; redm[half * 64 + rh] = mxhi; }
        __syncthreads();
        if (t < 64) {
            float mo = m_s[t];
            float mn = fmaxf(mo, fmaxf(redm[t], redm[64 + t]));
            float al = __expf(mo - mn);
            a_s[t] = al; m_s[t] = mn; l_s[t] *= al;
        }
        __syncthreads();

        float mlo = m_s[rl], mhi = m_s[rh], alo = a_s[rl], ahi = a_s[rh];
        float slo = 0.f, shi = 0.f;
        uint32_t afr[2][4];
#pragma unroll
        for (int ks = 0; ks < 2; ks++) {
#pragma unroll
            for (int jj = 0; jj < 2; jj++) {
                int nt = ks * 2 + jj;
                float p0 = __expf(s[nt][0] - mlo), p1 = __expf(s[nt][1] - mlo);
                float p2 = __expf(s[nt][2] - mhi), p3 = __expf(s[nt][3] - mhi);
                slo += p0 + p1; shi += p2 + p3;
                afr[ks][jj * 2 + 0] = packbf(p0, p1);
                afr[ks][jj * 2 + 1] = packbf(p2, p3);
            }
        }
        slo += __shfl_xor_sync(0xffffffff, slo, 1);
        slo += __shfl_xor_sync(0xffffffff, slo, 2);
        shi += __shfl_xor_sync(0xffffffff, shi, 1);
        shi += __shfl_xor_sync(0xffffffff, shi, 2);
        if ((lane & 3) == 0) { reds[half * 64 + rl] = slo; reds[half * 64 + rh] = shi; }

#pragma unroll
        for (int nt = 0; nt < 16; nt++) {
            o[nt][0] *= alo; o[nt][1] *= alo; o[nt][2] *= ahi; o[nt][3] *= ahi;
        }

#pragma unroll
        for (int ks = 0; ks < 2; ks++) {
#pragma unroll
            for (int nb = 0; nb < 8; nb++) {
                uint32_t b4[4];
                ldmT(b4, vsb + (wn2 + ks * 16 + (lane & 15)) * EF_PITCH
                         + nb * 32 + (lane >> 4) * 16);
                mma_bf16(o[2 * nb],     afr[ks], b4);
                mma_bf16(o[2 * nb + 1], afr[ks], b4 + 2);
            }
        }
        __syncthreads();
        if (t < 64) l_s[t] += reds[t] + reds[64 + t];
    }

    __syncthreads();
    if (half == 0) {
#pragma unroll
        for (int nt = 0; nt < 16; nt++) {
            float* plo = Obuf + rl * 132 + nt * 8 + (lane & 3) * 2;
            float* phi = Obuf + rh * 132 + nt * 8 + (lane & 3) * 2;
            plo[0] = o[nt][0]; plo[1] = o[nt][1];
            phi[0] = o[nt][2]; phi[1] = o[nt][3];
        }
    }
    __syncthreads();
    if (half == 1) {
#pragma unroll
        for (int nt = 0; nt < 16; nt++) {
            float* plo = Obuf + rl * 132 + nt * 8 + (lane & 3) * 2;
            float* phi = Obuf + rh * 132 + nt * 8 + (lane & 3) * 2;
            plo[0] += o[nt][0]; plo[1] += o[nt][1];
            phi[0] += o[nt][2]; phi[1] += o[nt][3];
        }
    }
    __syncthreads();
#pragma unroll
    for (int j = 0; j < 16; j++) {
        int id = t + 256 * j;
        int r = id >> 6, cp = id & 63;
        float inv = 1.f / l_s[r];
        float2 v = *(float2*)(Obuf + r * 132 + cp * 2);
        __nv_bfloat162 ob = __float22bfloat162_rn(make_float2(v.x * inv, v.y * inv));
        *(__nv_bfloat162*)(O + base + (size_t)(q0 + r) * 1024 + cp * 2) = ob;
    }
}

// ---------------- main flash (bf16 mma, HD=64, 2 CTA/SM, Obuf aliased) ------
#define MF_PITCH 144
#define MF_QS 0
#define MF_KV0 9216
#define MF_MS  46080
#define MF_LS  46336
#define MF_AS  46592
#define MF_RM  46848
#define MF_RS  47360
#define MF_SMEM 47872

__global__ __launch_bounds__(256, 2) void mflash_kernel(
    const __nv_bfloat16* __restrict__ Q, const __nv_bfloat16* __restrict__ K,
    const __nv_bfloat16* __restrict__ V, __nv_bfloat16* __restrict__ O,
    float scale)
{
    extern __shared__ char sm_[];
    float* Obuf = (float*)(sm_ + MF_KV0);
    float* m_s  = (float*)(sm_ + MF_MS);
    float* l_s  = (float*)(sm_ + MF_LS);
    float* a_s  = (float*)(sm_ + MF_AS);
    float* redm = (float*)(sm_ + MF_RM);
    float* reds = (float*)(sm_ + MF_RS);
    uint32_t smb = smem_u32(sm_);

    int t = threadIdx.x, lane = t & 31, wid = t >> 5;
    int half = wid >> 2, wm = (wid & 3) * 16, wn2 = half * 32;
    int slice = blockIdx.y;
    int sb = slice >> 4, h = slice & 15;
    size_t base = (size_t)sb * Sq * 1024 + (size_t)h * HD1;
    int q0 = blockIdx.x * 64;

#pragma unroll
    for (int j = 0; j < 2; j++) {
        int id = t + 256 * j;
        int r = id >> 3, c = id & 7;
        *(uint4*)(sm_ + MF_QS + r * MF_PITCH + c * 16) =
            *(const uint4*)(Q + base + (size_t)(q0 + r) * 1024 + c * 8);
    }
    if (t < 64) { m_s[t] = -1e30f; l_s[t] = 0.f; }

    {
#pragma unroll
        for (int j = 0; j < 2; j++) {
            int id = t + 256 * j;
            int r = id >> 3, c = id & 7;
            size_t g = base + (size_t)r * 1024 + c * 8;
            cp16(smb + MF_KV0 + r * MF_PITCH + c * 16, K + g);
            cp16(smb + MF_KV0 + 9216 + r * MF_PITCH + c * 16, V + g);
        }
        asm volatile("cp.async.commit_group;");
    }

    float o[8][4];
#pragma unroll
    for (int i = 0; i < 8; i++)
#pragma unroll
        for (int q = 0; q < 4; q++) o[i][q] = 0.f;

    int rl = wm + (lane >> 2), rh = rl + 8;
    int nq = lane >> 2, kr = lane & 3;
    const int NTILE = Sq / 64;

    for (int kt = 0; kt < NTILE; kt++) {
        __syncthreads();
        if (kt + 1 < NTILE) {
            uint32_t stg = smb + MF_KV0 + ((kt + 1) & 1) * 18432;
#pragma unroll
            for (int j = 0; j < 2; j++) {
                int id = t + 256 * j;
                int r = id >> 3, c = id & 7;
                size_t g = base + (size_t)((kt + 1) * 64 + r) * 1024 + c * 8;
                cp16(stg + r * MF_PITCH + c * 16, K + g);
                cp16(stg + 9216 + r * MF_PITCH + c * 16, V + g);
            }
        }
        asm volatile("cp.async.commit_group;");
        asm volatile("cp.async.wait_group 1;");
        __syncthreads();

        uint32_t ksb = smb + MF_KV0 + (kt & 1) * 18432;
        uint32_t vsb = ksb + 9216;
        const char* kcp = sm_ + (ksb - smb);

        float s[4][4];
#pragma unroll
        for (int nt = 0; nt < 4; nt++)
#pragma unroll
            for (int q = 0; q < 4; q++) s[nt][q] = 0.f;
#pragma unroll
        for (int ks = 0; ks < 4; ks++) {
            uint32_t af[4];
            ldmA(af, smb + MF_QS + (wm + (lane & 15)) * MF_PITCH + ks * 32 + (lane >> 4) * 16);
#pragma unroll
            for (int nt = 0; nt < 4; nt++) {
                const char* p = kcp + (wn2 + nt * 8 + nq) * MF_PITCH + ks * 32 + kr * 4;
                uint32_t bb[2];
                bb[0] = *(const uint32_t*)p;
                bb[1] = *(const uint32_t*)(p + 16);
                mma_bf16(s[nt], af, bb);
            }
        }

        float mxlo = -1e30f, mxhi = -1e30f;
#pragma unroll
        for (int nt = 0; nt < 4; nt++) {
            s[nt][0] *= scale; s[nt][1] *= scale; s[nt][2] *= scale; s[nt][3] *= scale;
            mxlo = fmaxf(mxlo, fmaxf(s[nt][0], s[nt][1]));
            mxhi = fmaxf(mxhi, fmaxf(s[nt][2], s[nt][3]));
        }
        mxlo = fmaxf(mxlo, __shfl_xor_sync(0xffffffff, mxlo, 1));
        mxlo = fmaxf(mxlo, __shfl_xor_sync(0xffffffff, mxlo, 2));
        mxhi = fmaxf(mxhi, __shfl_xor_sync(0xffffffff, mxhi, 1));
        mxhi = fmaxf(mxhi, __shfl_xor_sync(0xffffffff, mxhi, 2));
        if ((lane & 3) == 0) { redm[half * 64 + rl] = mxlo; redm[half * 64 + rh] = mxhi; }
        __syncthreads();
        if (t < 64) {
            float mo = m_s[t];
            float mn = fmaxf(mo, fmaxf(redm[t], redm[64 + t]));
            float al = __expf(mo - mn);
            a_s[t] = al; m_s[t] = mn; l_s[t] *= al;
        }
        __syncthreads();

        float mlo = m_s[rl], mhi = m_s[rh], alo = a_s[rl], ahi = a_s[rh];
        float slo = 0.f, shi = 0.f;
        uint32_t afr[2][4];
#pragma unroll
        for (int ks = 0; ks < 2; ks++) {
#pragma unroll
            for (int jj = 0; jj < 2; jj++) {
                int nt = ks * 2 + jj;
                float p0 = __expf(s[nt][0] - mlo), p1 = __expf(s[nt][1] - mlo);
                float p2 = __expf(s[nt][2] - mhi), p3 = __expf(s[nt][3] - mhi);
                slo += p0 + p1; shi += p2 + p3;
                afr[ks][jj * 2 + 0] = packbf(p0, p1);
                afr[ks][jj * 2 + 1] = packbf(p2, p3);
            }
        }
        slo += __shfl_xor_sync(0xffffffff, slo, 1);
        slo += __shfl_xor_sync(0xffffffff, slo, 2);
        shi += __shfl_xor_sync(0xffffffff, shi, 1);
        shi += __shfl_xor_sync(0xffffffff, shi, 2);
        if ((lane & 3) == 0) { reds[half * 64 + rl] = slo; reds[half * 64 + rh] = shi; }

#pragma unroll
        for (int nt = 0; nt < 8; nt++) {
            o[nt][0] *= alo; o[nt][1] *= alo; o[nt][2] *= ahi; o[nt][3] *= ahi;
        }

#pragma unroll
        for (int ks = 0; ks < 2; ks++) {
#pragma unroll
            for (int nb = 0; nb < 4; nb++) {
                uint32_t b4[4];
                ldmT(b4, vsb + (wn2 + ks * 16 + (lane & 15)) * MF_PITCH
                         + nb * 32 + (lane >> 4) * 16);
                mma_bf16(o[2 * nb],     afr[ks], b4);
                mma_bf16(o[2 * nb + 1], afr[ks], b4 + 2);
            }
        }
        __syncthreads();
        if (t < 64) l_s[t] += reds[t] + reds[64 + t];
    }

    __syncthreads();
    if (half == 0) {
#pragma unroll
        for (int nt = 0; nt < 8; nt++) {
            float* plo = Obuf + rl * 68 + nt * 8 + (lane & 3) * 2;
            float* phi = Obuf + rh * 68 + nt * 8 + (lane & 3) * 2;
            plo[0] = o[nt][0]; plo[1] = o[nt][1];
            phi[0] = o[nt][2]; phi[1] = o[nt][3];
        }
    }
    __syncthreads();
    if (half == 1) {
#pragma unroll
        for (int nt = 0; nt < 8; nt++) {
            float* plo = Obuf + rl * 68 + nt * 8 + (lane & 3) * 2;
            float* phi = Obuf + rh * 68 + nt * 8 + (lane & 3) * 2;
            plo[0] += o[nt][0]; plo[1] += o[nt][1];
            phi[0] += o[nt][2]; phi[1] += o[nt][3];
        }
    }
    __syncthreads();
#pragma unroll
    for (int j = 0; j < 8; j++) {
        int id = t + 256 * j;
        int r = id >> 5, cp = id & 31;
        float inv = 1.f / l_s[r];
        float2 v = *(float2*)(Obuf + r * 68 + cp * 2);
        __nv_bfloat162 ob = __float22bfloat162_rn(make_float2(v.x * inv, v.y * inv));
        *(__nv_bfloat162*)(O + base + (size_t)(q0 + r) * 1024 + cp * 2) = ob;
    }
}

// ---------------- fp32 -> bf16 convert (ILP-4, uint4 stores) ----------------
__global__ __launch_bounds__(256) void cvt_kernel(
    const float4* __restrict__ s, uint4* __restrict__ h, int n4)
{
#pragma unroll
    for (int j = 0; j < 4; j++) {
        int i = blockIdx.x * 2048 + j * 512 + threadIdx.x * 2;
        if (i < n4) {
            float4 v0 = s[i], v1 = s[i + 1];
            uint4 hh;
            hh.x = packbf(v0.x, v0.y); hh.y = packbf(v0.z, v0.w);
            hh.z = packbf(v1.x, v1.y); hh.w = packbf(v1.z, v1.w);
            h[i >> 1] = hh;
        }
    }
}

__global__ __launch_bounds__(256) void cvt4_kernel(
    const float4* __restrict__ s0, const float4* __restrict__ s1,
    const float4* __restrict__ s2, const float4* __restrict__ s3,
    uint4* __restrict__ d0, uint4* __restrict__ d1,
    uint4* __restrict__ d2, uint4* __restrict__ d3, int n4)
{
    const float4* s; uint4* d;
    switch (blockIdx.y) {
        case 0:  s = s0; d = d0; break;
        case 1:  s = s1; d = d1; break;
        case 2:  s = s2; d = d2; break;
        default: s = s3; d = d3; break;
    }
#pragma unroll
    for (int j = 0; j < 4; j++) {
        int i = blockIdx.x * 2048 + j * 512 + threadIdx.x * 2;
        if (i < n4) {
            float4 v0 = s[i], v1 = s[i + 1];
            uint4 hh;
            hh.x = packbf(v0.x, v0.y); hh.y = packbf(v0.z, v0.w);
            hh.z = packbf(v1.x, v1.y); hh.w = packbf(v1.z, v1.w);
            d[i >> 1] = hh;
        }
    }
}

// ---------------- zero (ein + stats merged) ----------------
__global__ void zero_ein_kernel() {
    if (blockIdx.x == 0 && threadIdx.x < 32) {
        int t = threadIdx.x;
        if (t < NE) { g_Psum[t] = 0.f; g_fcnt[t] = 0.f; }
        if (t == 0) g_zsum = 0.f;
    }
    size_t n = EINSZ / 8;
    uint4 z = make_uint4(0, 0, 0, 0);
    uint4* ph = (uint4*)g_einh;
    for (size_t i = blockIdx.x * (size_t)blockDim.x + threadIdx.x; i < n;
         i += (size_t)gridDim.x * blockDim.x) ph[i] = z;
}

// ---------------- block reduce ----------------
__device__ __forceinline__ void block_reduce2(float& s, float& s2) {
    __shared__ float rs[8], rs2[8];
#pragma unroll
    for (int o = 16; o > 0; o >>= 1) {
        s  += __shfl_xor_sync(0xffffffff, s, o);
        s2 += __shfl_xor_sync(0xffffffff, s2, o);
    }
    int lane = threadIdx.x & 31, w = threadIdx.x >> 5;
    if (lane == 0) { rs[w] = s; rs2[w] = s2; }
    __syncthreads();
    float ts = 0.f, ts2 = 0.f;
#pragma unroll
    for (int i = 0; i < 8; i++) { ts += rs[i]; ts2 += rs2[i]; }
    s = ts; s2 = ts2;
}

// ---------------- LN1 + gate (fused) ----------------
__global__ __launch_bounds__(256) void ln1gate_kernel(
    const float* __restrict__ x, const float* __restrict__ g,
    const float* __restrict__ b, const float* __restrict__ gateW)
{
    __shared__ float ga[8][NE];
    size_t tok = blockIdx.x;
    int t = threadIdx.x, lane = t & 31, w = t >> 5;
    float v[4], s = 0.f, s2 = 0.f;
#pragma unroll
    for (int u = 0; u < 4; u++) {
        int j = t + u * 256;
        float val = x[tok * Dm + j] + g_attn[tok * Dm + j];
        v[u] = val; s += val; s2 += val * val;
    }
    block_reduce2(s, s2);
    float mean = s * (1.f / Dm);
    float var  = s2 * (1.f / Dm) - mean * mean;
    float inv  = rsqrtf(var + 1e-5f);

    float acc[NE];
#pragma unroll
    for (int e = 0; e < NE; e++) acc[e] = 0.f;
#pragma unroll
    for (int u = 0; u < 4; u++) {
        int j = t + u * 256;
        float x1v = (v[u] - mean) * inv * g[j] + b[j];
        g_x1[tok * Dm + j] = x1v;
        const float* wr = gateW + (size_t)j * NE;
#pragma unroll
        for (int e = 0; e < NE; e++) acc[e] += x1v * wr[e];
    }
#pragma unroll
    for (int e = 0; e < NE; e++)
#pragma unroll
        for (int o = 16; o > 0; o >>= 1)
            acc[e] += __shfl_xor_sync(0xffffffff, acc[e], o);
    if (lane == 0)
#pragma unroll
        for (int e = 0; e < NE; e++) ga[w][e] = acc[e];
    __syncthreads();

    if (t == 0) {
        float lg[NE];
#pragma unroll
        for (int e = 0; e < NE; e++) {
            float sv = 0.f;
#pragma unroll
            for (int i = 0; i < 8; i++) sv += ga[i][e];
            lg[e] = sv;
        }
        float mx = lg[0];
#pragma unroll
        for (int e = 1; e < NE; e++) mx = fmaxf(mx, lg[e]);
        float p[NE], se = 0.f;
#pragma unroll
        for (int e = 0; e < NE; e++) { p[e] = __expf(lg[e] - mx); se += p[e]; }
        float invs = 1.f / se;
        float lse = mx + logf(se);
        atomicAdd(&g_zsum, lse * lse);
        int i0 = 0, i1 = -1;
        float b0 = -1.f, b1 = -1.f;
#pragma unroll
        for (int e = 0; e < NE; e++) {
            float pe = p[e] * invs;
            atomicAdd(&g_Psum[e], pe);
            if (pe > b0) { b1 = b0; i1 = i0; b0 = pe; i0 = e; }
            else if (pe > b1) { b1 = pe; i1 = e; }
        }
        atomicAdd(&g_fcnt[i0], 1.f);
        g_i0[tok] = i0; g_i1[tok] = i1;
        g_g0[tok] = b0; g_g1[tok] = b1;
    }
}

// ---------------- routing positions ----------------
__global__ __launch_bounds__(256) void pos_kernel() {
    int warp = threadIdx.x >> 5, lane = threadIdx.x & 31;
    if (warp >= Bt) return;
    int b = warp;
    unsigned lt = (1u << lane) - 1u;
    int cnt[NE];
#pragma unroll
    for (int e = 0; e < NE; e++) cnt[e] = 0;

    for (int ch = 0; ch < Sq / 32; ch++) {
        int tok = b * Sq + ch * 32 + lane;
        int e0 = g_i0[tok];
        int myp = 0;
#pragma unroll
        for (int e = 0; e < NE; e++) {
            unsigned m = __ballot_sync(0xffffffff, e0 == e);
            if (e0 == e) myp = cnt[e] + __popc(m & lt);
            cnt[e] += __popc(m);
        }
        g_k0[tok] = (myp < CAP) ? 1 : 0;
        g_p0[tok] = min(myp, CAP - 1);
    }
    for (int ch = 0; ch < Sq / 32; ch++) {
        int tok = b * Sq + ch * 32 + lane;
        int e1 = g_i1[tok];
        bool valid = g_g1[tok] > 0.2f;
        int myp = 0;
#pragma unroll
        for (int e = 0; e < NE; e++) {
            unsigned m = __ballot_sync(0xffffffff, valid && (e1 == e));
            if (valid && (e1 == e)) myp = cnt[e] + __popc(m & lt);
            cnt[e] += __popc(m);
        }
        bool keep = valid && (myp < CAP);
        g_k1[tok] = keep ? 1 : 0;
        g_p1[tok] = valid ? min(myp, CAP - 1) : 0;
    }
}

// ---------------- scatter (x1 fp32 -> einh bf16) ----------------
__global__ __launch_bounds__(256) void scatter_kernel() {
    int idx = blockIdx.x;
    int tok = idx >> 1, slot = idx & 1;
    int keep = slot ? g_k1[tok] : g_k0[tok];
    if (!keep) return;
    int e = slot ? g_i1[tok] : g_i0[tok];
    int p = slot ? g_p1[tok] : g_p0[tok];
    int b = tok / Sq;
    const float4* src = (const float4*)(g_x1 + (size_t)tok * Dm);
    size_t ro = (((size_t)e * Bt + b) * CAP + p) * Dm;
    uint2* dh = (uint2*)(g_einh + ro);
    float4 v = src[threadIdx.x];
    uint2 hh;
    hh.x = packbf(v.x, v.y);
    hh.y = packbf(v.z, v.w);
    dh[threadIdx.x] = hh;
}

// ---------------- combine + LN2 ----------------
__global__ __launch_bounds__(256) void combine_ln_kernel(
    const float* __restrict__ g2, const float* __restrict__ b2,
    float* __restrict__ out)
{
    size_t tok = blockIdx.x;
    int t = threadIdx.x;
    int b = (int)(tok >> 10);
    float w0 = g_k0[tok] ? g_g0[tok] : 0.f;
    float w1 = g_k1[tok] ? g_g1[tok] : 0.f;
    const __nv_bfloat16* r0 = g_eoutb + (((size_t)g_i0[tok] * Bt + b) * CAP + g_p0[tok]) * Dm;
    const __nv_bfloat16* r1 = g_eoutb + (((size_t)g_i1[tok] * Bt + b) * CAP + g_p1[tok]) * Dm;

    float v[4], s = 0.f, s2 = 0.f;
#pragma unroll
    for (int u = 0; u < 4; u++) {
        int j = t + u * 256;
        float val = g_x1[tok * Dm + j]
                  + w0 * __bfloat162float(r0[j]) + w1 * __bfloat162float(r1[j]);
        v[u] = val; s += val; s2 += val * val;
    }
    block_reduce2(s, s2);
    float mean = s * (1.f / Dm);
    float var  = s2 * (1.f / Dm) - mean * mean;
    float inv  = rsqrtf(var + 1e-5f);
#pragma unroll
    for (int u = 0; u < 4; u++) {
        int j = t + u * 256;
        out[tok * Dm + j] = (v[u] - mean) * inv * g2[j] + b2[j];
    }
}

// ---------------- finalize aux ----------------
__global__ void finalize_kernel(float* __restrict__ out) {
    if (threadIdx.x == 0 && blockIdx.x == 0) {
        float invN = 1.f / (float)NT;
        float sfp = 0.f;
#pragma unroll
        for (int e = 0; e < NE; e++)
            sfp += (g_fcnt[e] * invN) * (g_Psum[e] * invN);
        float bal = 0.01f * (float)NE * sfp;
        float zl  = 0.001f * g_zsum * invN;
        out[NTD + 0] = bal + zl;
        out[NTD + 1] = bal;
        out[NTD + 2] = zl;
    }
}

// ---------------- host launcher ----------------
extern "C" void kernel_launch(void* const* d_in, const int* in_sizes, int n_in,
                              void* d_out, int out_size)
{
    const float* x      = (const float*)d_in[0];
    const float* Wq     = (const float*)d_in[1];
    const float* Wk     = (const float*)d_in[2];
    const float* Wv     = (const float*)d_in[3];
    const float* Wo     = (const float*)d_in[4];
    const float* bq     = (const float*)d_in[5];
    const float* bk     = (const float*)d_in[6];
    const float* bv     = (const float*)d_in[7];
    const float* bo     = (const float*)d_in[8];
    const float* ln1_g  = (const float*)d_in[9];
    const float* ln1_b  = (const float*)d_in[10];
    const float* ln2_g  = (const float*)d_in[11];
    const float* ln2_b  = (const float*)d_in[12];
    const float* gate_W = (const float*)d_in[13];
    const float* eWq    = (const float*)d_in[14];
    const float* eWk    = (const float*)d_in[15];
    const float* eWv    = (const float*)d_in[16];
    const float* eWo    = (const float*)d_in[17];
    float* out = (float*)d_out;

    void *pattn, *px1, *peoutb, *pxh, *pqkvh, *poh;
    void *peinh, *peqkv, *peoh;
    void *pwqkvh, *pwoh, *pewh, *pewoh, *pbqkv;
    cudaGetSymbolAddress(&pattn, g_attn);   cudaGetSymbolAddress(&px1, g_x1);
    cudaGetSymbolAddress(&peoutb, g_eoutb); cudaGetSymbolAddress(&pxh, g_xh);
    cudaGetSymbolAddress(&pqkvh, g_qkvh);   cudaGetSymbolAddress(&poh, g_oh);
    cudaGetSymbolAddress(&peinh, g_einh);   cudaGetSymbolAddress(&peqkv, g_eqkv);
    cudaGetSymbolAddress(&peoh, g_eoh);
    cudaGetSymbolAddress(&pwqkvh, g_wqkvh); cudaGetSymbolAddress(&pwoh, g_woh);
    cudaGetSymbolAddress(&pewh, g_ewh);     cudaGetSymbolAddress(&pewoh, g_ewoh);
    cudaGetSymbolAddress(&pbqkv, g_bqkv);

    cudaFuncSetAttribute(gemm_mma_kernel<0>, cudaFuncAttributeMaxDynamicSharedMemorySize, GEMM_SMEM);
    cudaFuncSetAttribute(gemm_mma_kernel<1>, cudaFuncAttributeMaxDynamicSharedMemorySize, GEMM_SMEM);
    cudaFuncSetAttribute(mflash_kernel, cudaFuncAttributeMaxDynamicSharedMemorySize, MF_SMEM);
    cudaFuncSetAttribute(eflash_kernel, cudaFuncAttributeMaxDynamicSharedMemorySize, EF_SMEM);

    zero_ein_kernel<<<2048, 256>>>();

    cudaMemcpyAsync((float*)pbqkv,          bq, Dm * sizeof(float), cudaMemcpyDeviceToDevice);
    cudaMemcpyAsync((float*)pbqkv + Dm,     bk, Dm * sizeof(float), cudaMemcpyDeviceToDevice);
    cudaMemcpyAsync((float*)pbqkv + 2 * Dm, bv, Dm * sizeof(float), cudaMemcpyDeviceToDevice);

    __nv_bfloat16* wqkv = (__nv_bfloat16*)pwqkvh;
    __nv_bfloat16* ewh  = (__nv_bfloat16*)pewh;
    const int WB1 = (int)(DMDM / 4);
    cvt4_kernel<<<dim3((WB1 + 2047) / 2048, 4), 256>>>(
        (const float4*)Wq, (const float4*)Wk, (const float4*)Wv, (const float4*)Wo,
        (uint4*)wqkv, (uint4*)(wqkv + DMDM), (uint4*)(wqkv + 2 * DMDM), (uint4*)pwoh, WB1);
    const int WBE = (int)(NE * DMDM / 4);
    cvt4_kernel<<<dim3((WBE + 2047) / 2048, 4), 256>>>(
        (const float4*)eWq, (const float4*)eWk, (const float4*)eWv, (const float4*)eWo,
        (uint4*)ewh, (uint4*)(ewh + NE * DMDM), (uint4*)(ewh + 2 * NE * DMDM), (uint4*)pewoh, WBE);

    cvt_kernel<<<(int)(NTD / 4 / 2048), 256>>>((const float4*)x, (uint4*)pxh, (int)(NTD / 4));

    // main QKV: BM=256 tiles, z in [0,3)
    gemm_mma_kernel<1><<<dim3(Dm / 128, NT / 256, 3), 512, GEMM_SMEM>>>(
        (__nv_bfloat16*)pxh, wqkv, (const float*)pbqkv, pqkvh,
        NT, Dm, Dm, 0, DMDM, NTD, Dm, 3);

    __nv_bfloat16* qkv = (__nv_bfloat16*)pqkvh;
    mflash_kernel<<<dim3(Sq / 64, Bt * NH), 256, MF_SMEM>>>(
        qkv, qkv + NTD, qkv + 2 * NTD, (__nv_bfloat16*)poh, 0.125f);

    gemm_mma_kernel<0><<<dim3(Dm / 128, NT / 256, 1), 512, GEMM_SMEM>>>(
        (__nv_bfloat16*)poh, (__nv_bfloat16*)pwoh, bo, pattn,
        NT, Dm, Dm, 0, 0, 0, 0, 1);

    ln1gate_kernel<<<NT, 256>>>(x, ln1_g, ln1_b, gate_W);
    pos_kernel<<<1, 256>>>();
    scatter_kernel<<<NT * 2, 256>>>();

    size_t sA = (size_t)EROWS * Dm;
    gemm_mma_kernel<1><<<dim3(Dm / 128, EROWS / 256, 24), 512, GEMM_SMEM>>>(
        (__nv_bfloat16*)peinh, ewh, nullptr, peqkv,
        EROWS, Dm, Dm, sA, DMDM, sA, 0, NE);

    __nv_bfloat16* eqkv = (__nv_bfloat16*)peqkv;
    eflash_kernel<<<dim3(CAP / 64, NE * Bt * NHM), 256, EF_SMEM>>>(
        eqkv, eqkv + EINSZ, eqkv + 2 * EINSZ, (__nv_bfloat16*)peoh, 0.0883883476483184f);

    gemm_mma_kernel<1><<<dim3(Dm / 128, EROWS / 256, NE), 512, GEMM_SMEM>>>(
        (__nv_bfloat16*)peoh, (__nv_bfloat16*)pewoh, nullptr, peoutb,
        EROWS, Dm, Dm, sA, DMDM, sA, 0, NE);

    combine_ln_kernel<<<NT, 256>>>(ln2_g, ln2_b, out);
    finalize_kernel<<<1, 32>>>(out);
}

// round 16
// speedup vs baseline: 1.0567x; 1.0567x over previous
#include <cuda_runtime.h>
#include <cuda_bf16.h>
#include <math.h>
#include <stdint.h>

// ---------------- problem dims ----------------
#define Bt   8
#define Sq   1024
#define Dm   1024
#define NH   16
#define HD1  64
#define NE   8
#define NHM  8
#define HDM  128
#define CAP  320
#define NT   (Bt*Sq)
#define NTD  ((size_t)NT*Dm)
#define EROWS (Bt*CAP)
#define EINSZ ((size_t)NE*Bt*CAP*Dm)
#define DMDM ((size_t)Dm*Dm)

// ---------------- scratch ----------------
static __device__ float g_x1[NTD];

static __device__ __nv_bfloat16 g_attnb[NTD];
static __device__ __nv_bfloat16 g_xh[NTD];
static __device__ __nv_bfloat16 g_qkvh[3*NTD];
static __device__ __nv_bfloat16 g_oh[NTD];
static __device__ __nv_bfloat16 g_einh[EINSZ];
static __device__ __nv_bfloat16 g_eqkv[3*EINSZ];
static __device__ __nv_bfloat16 g_eoh[EINSZ];
static __device__ __nv_bfloat16 g_eoutb[EINSZ];
static __device__ __nv_bfloat16 g_wqkvh[3*DMDM];
static __device__ __nv_bfloat16 g_woh[DMDM];
static __device__ __nv_bfloat16 g_ewh[3*NE*DMDM];
static __device__ __nv_bfloat16 g_ewoh[NE*DMDM];
static __device__ float g_bqkv[3*Dm];

static __device__ int   g_i0[NT], g_i1[NT];
static __device__ float g_g0[NT], g_g1[NT];
static __device__ int   g_p0[NT], g_p1[NT];
static __device__ int   g_k0[NT], g_k1[NT];

static __device__ float g_Psum[NE];
static __device__ float g_fcnt[NE];
static __device__ float g_zsum;

// ---------------- PTX helpers ----------------
__device__ __forceinline__ uint32_t smem_u32(const void* p) {
    uint32_t a;
    asm("{ .reg .u64 t; cvta.to.shared.u64 t, %1; cvt.u32.u64 %0, t; }" : "=r"(a) : "l"(p));
    return a;
}
__device__ __forceinline__ void cp16(uint32_t dst, const void* src) {
    asm volatile("cp.async.cg.shared.global [%0], [%1], 16;" :: "r"(dst), "l"(src));
}
__device__ __forceinline__ void ldmA(uint32_t* a, uint32_t addr) {
    asm volatile("ldmatrix.sync.aligned.m8n8.x4.shared.b16 {%0,%1,%2,%3}, [%4];"
        : "=r"(a[0]), "=r"(a[1]), "=r"(a[2]), "=r"(a[3]) : "r"(addr));
}
__device__ __forceinline__ void ldmT(uint32_t* a, uint32_t addr) {
    asm volatile("ldmatrix.sync.aligned.m8n8.x4.trans.shared.b16 {%0,%1,%2,%3}, [%4];"
        : "=r"(a[0]), "=r"(a[1]), "=r"(a[2]), "=r"(a[3]) : "r"(addr));
}
__device__ __forceinline__ void mma_bf16(float* d, const uint32_t* a, const uint32_t* b) {
    asm volatile(
        "mma.sync.aligned.m16n8k16.row.col.f32.bf16.bf16.f32 "
        "{%0,%1,%2,%3}, {%4,%5,%6,%7}, {%8,%9}, {%0,%1,%2,%3};"
        : "+f"(d[0]), "+f"(d[1]), "+f"(d[2]), "+f"(d[3])
        : "r"(a[0]), "r"(a[1]), "r"(a[2]), "r"(a[3]), "r"(b[0]), "r"(b[1]));
}
__device__ __forceinline__ uint32_t packbf(float a, float b) {
    __nv_bfloat162 v = __float22bfloat162_rn(make_float2(a, b));
    return *(uint32_t*)&v;
}

// ---------------- GEMM via mma.sync (bf16, BK=64, B in natural [K,N]) -------
#define BK 64
#define ROWA 144
#define ROWBB 272
#define ASTG (128*ROWA)
#define BSTG (64*ROWBB)
#define STG2 (ASTG+BSTG)
#define NSTG 3
#define GEMM_SMEM (NSTG*STG2)

template <int OUTBF>
__global__ __launch_bounds__(256, 2) void gemm_mma_kernel(
    const __nv_bfloat16* __restrict__ A, const __nv_bfloat16* __restrict__ W,
    const float* __restrict__ bias, void* __restrict__ Cv,
    int M, int N, int K, size_t sA, size_t sB, size_t sC, size_t sbias, int zmod)
{
    extern __shared__ char sm_[];
    uint32_t smb = smem_u32(sm_);

    int t = threadIdx.x, lane = t & 31, wid = t >> 5;
    int n0 = blockIdx.x * 128, m0 = blockIdx.y * 128;
    int z = blockIdx.z;
    A += (size_t)(z % zmod) * sA;
    W += (size_t)z * sB;
    if (bias) bias += (size_t)z * sbias;

    int wm = (wid & 3) * 32;
    int wn = (wid >> 2) * 64;
    const int NC = K / BK;

    float acc[2][8][4];
#pragma unroll
    for (int i = 0; i < 2; i++)
#pragma unroll
        for (int j = 0; j < 8; j++)
#pragma unroll
            for (int q = 0; q < 4; q++) acc[i][j][q] = 0.f;

    int rb = t >> 3, c8 = t & 7;
    const __nv_bfloat16* Ap = A + (size_t)(m0 + rb) * K + c8 * 8;
    uint32_t waA = (uint32_t)rb * ROWA + c8 * 16;
    const size_t rstepA = (size_t)32 * K;
    int rB = t >> 4, cB = t & 15;
    const __nv_bfloat16* Wp = W + (size_t)rB * N + n0 + cB * 8;
    uint32_t waB = (uint32_t)rB * ROWBB + cB * 16;
    const size_t rstepB = (size_t)16 * N;

#pragma unroll
    for (int s = 0; s < 2; s++) {
        uint32_t stg = smb + s * STG2;
        int kc = s * BK;
#pragma unroll
        for (int j = 0; j < 4; j++) {
            cp16(stg + waA + j * (32 * ROWA), Ap + kc + j * rstepA);
            cp16(stg + ASTG + waB + j * (16 * ROWBB), Wp + (size_t)kc * N + j * rstepB);
        }
        asm volatile("cp.async.commit_group;");
    }

    uint32_t a_row = (uint32_t)(wm + (lane & 15)) * ROWA + (lane >> 4) * 16;
    uint32_t b_col = (uint32_t)(lane & 15) * ROWBB + wn * 2 + (lane >> 4) * 16;

    int sidx = 0;
    for (int c = 0; c < NC; c++) {
        asm volatile("cp.async.wait_group 1;");
        __syncthreads();
        if (c + 2 < NC) {
            int sn = sidx + 2; if (sn >= NSTG) sn -= NSTG;
            uint32_t stg = smb + sn * STG2;
            int kc = (c + 2) * BK;
#pragma unroll
            for (int j = 0; j < 4; j++) {
                cp16(stg + waA + j * (32 * ROWA), Ap + kc + j * rstepA);
                cp16(stg + ASTG + waB + j * (16 * ROWBB), Wp + (size_t)kc * N + j * rstepB);
            }
        }
        asm volatile("cp.async.commit_group;");

        uint32_t ab = smb + sidx * STG2;
        uint32_t bb = ab + ASTG;

#pragma unroll
        for (int ks = 0; ks < 4; ks++) {
            uint32_t afr[2][4];
#pragma unroll
            for (int mt = 0; mt < 2; mt++)
                ldmA(afr[mt], ab + a_row + mt * (16 * ROWA) + ks * 32);

            uint32_t bfr[8][2];
#pragma unroll
            for (int nb = 0; nb < 4; nb++) {
                uint32_t q[4];
                ldmT(q, bb + b_col + ks * (16 * ROWBB) + nb * 32);
                bfr[nb * 2][0]     = q[0]; bfr[nb * 2][1]     = q[1];
                bfr[nb * 2 + 1][0] = q[2]; bfr[nb * 2 + 1][1] = q[3];
            }
#pragma unroll
            for (int mt = 0; mt < 2; mt++)
#pragma unroll
                for (int nt = 0; nt < 8; nt++)
                    mma_bf16(acc[mt][nt], afr[mt], bfr[nt]);
        }
        if (++sidx == NSTG) sidx = 0;
    }

#pragma unroll
    for (int mt = 0; mt < 2; mt++) {
        int m = m0 + wm + mt * 16 + (lane >> 2);
#pragma unroll
        for (int nt = 0; nt < 8; nt++) {
            int n = n0 + wn + nt * 8 + (lane & 3) * 2;
            float bv0 = bias ? bias[n] : 0.f;
            float bv1 = bias ? bias[n + 1] : 0.f;
            float v0 = acc[mt][nt][0] + bv0, v1 = acc[mt][nt][1] + bv1;
            float v2 = acc[mt][nt][2] + bv0, v3 = acc[mt][nt][3] + bv1;
            if (OUTBF == 0) {
                float* C = (float*)Cv + (size_t)z * sC;
                *(float2*)&C[(size_t)m * N + n]       = make_float2(v0, v1);
                *(float2*)&C[(size_t)(m + 8) * N + n] = make_float2(v2, v3);
            } else {
                __nv_bfloat16* C = (__nv_bfloat16*)Cv + (size_t)z * sC;
                *(uint32_t*)&C[(size_t)m * N + n]       = packbf(v0, v1);
                *(uint32_t*)&C[(size_t)(m + 8) * N + n] = packbf(v2, v3);
            }
        }
    }
}

// ---------------- expert flash (bf16 mma, HD=128, 2 CTA/SM, Obuf aliased) ---
#define EF_PITCH 272
#define EF_QS 0
#define EF_KV0 17408
#define EF_MS  87040
#define EF_LS  87296
#define EF_AS  87552
#define EF_RM  87808
#define EF_RS  88320
#define EF_SMEM 88832

__global__ __launch_bounds__(256, 2) void eflash_kernel(
    const __nv_bfloat16* __restrict__ Q, const __nv_bfloat16* __restrict__ K,
    const __nv_bfloat16* __restrict__ V, __nv_bfloat16* __restrict__ O,
    float scale)
{
    extern __shared__ char sm_[];
    float* Obuf = (float*)(sm_ + EF_KV0);
    float* m_s  = (float*)(sm_ + EF_MS);
    float* l_s  = (float*)(sm_ + EF_LS);
    float* a_s  = (float*)(sm_ + EF_AS);
    float* redm = (float*)(sm_ + EF_RM);
    float* reds = (float*)(sm_ + EF_RS);
    uint32_t smb = smem_u32(sm_);

    int t = threadIdx.x, lane = t & 31, wid = t >> 5;
    int half = wid >> 2, wm = (wid & 3) * 16, wn2 = half * 32;
    int slice = blockIdx.y;
    int sb = slice >> 3, h = slice & 7;
    size_t base = (size_t)sb * CAP * 1024 + (size_t)h * HDM;
    int q0 = blockIdx.x * 64;

#pragma unroll
    for (int j = 0; j < 4; j++) {
        int id = t + 256 * j;
        int r = id >> 4, c = id & 15;
        *(uint4*)(sm_ + EF_QS + r * EF_PITCH + c * 16) =
            *(const uint4*)(Q + base + (size_t)(q0 + r) * 1024 + c * 8);
    }
    if (t < 64) { m_s[t] = -1e30f; l_s[t] = 0.f; }

    {
#pragma unroll
        for (int j = 0; j < 4; j++) {
            int id = t + 256 * j;
            int rr = id >> 4, cc = id & 15;
            size_t g = base + (size_t)rr * 1024 + cc * 8;
            cp16(smb + EF_KV0 + rr * EF_PITCH + cc * 16, K + g);
            cp16(smb + EF_KV0 + 17408 + rr * EF_PITCH + cc * 16, V + g);
        }
        asm volatile("cp.async.commit_group;");
    }

    float o[16][4];
#pragma unroll
    for (int i = 0; i < 16; i++)
#pragma unroll
        for (int q = 0; q < 4; q++) o[i][q] = 0.f;

    int rl = wm + (lane >> 2), rh = rl + 8;
    int nq = lane >> 2, kr = lane & 3;
    const int NTILE = CAP / 64;

    for (int kt = 0; kt < NTILE; kt++) {
        __syncthreads();
        if (kt + 1 < NTILE) {
            uint32_t stg = smb + EF_KV0 + ((kt + 1) & 1) * 34816;
#pragma unroll
            for (int j = 0; j < 4; j++) {
                int id = t + 256 * j;
                int rr = id >> 4, cc = id & 15;
                size_t g = base + (size_t)((kt + 1) * 64 + rr) * 1024 + cc * 8;
                cp16(stg + rr * EF_PITCH + cc * 16, K + g);
                cp16(stg + 17408 + rr * EF_PITCH + cc * 16, V + g);
            }
        }
        asm volatile("cp.async.commit_group;");
        asm volatile("cp.async.wait_group 1;");
        __syncthreads();

        uint32_t ksb = smb + EF_KV0 + (kt & 1) * 34816;
        uint32_t vsb = ksb + 17408;
        const char* kcp = sm_ + (ksb - smb);

        float s[4][4];
#pragma unroll
        for (int nt = 0; nt < 4; nt++)
#pragma unroll
            for (int q = 0; q < 4; q++) s[nt][q] = 0.f;
#pragma unroll
        for (int ks = 0; ks < 8; ks++) {
            uint32_t af[4];
            ldmA(af, smb + EF_QS + (wm + (lane & 15)) * EF_PITCH + ks * 32 + (lane >> 4) * 16);
#pragma unroll
            for (int nt = 0; nt < 4; nt++) {
                const char* p = kcp + (wn2 + nt * 8 + nq) * EF_PITCH + ks * 32 + kr * 4;
                uint32_t bb[2];
                bb[0] = *(const uint32_t*)p;
                bb[1] = *(const uint32_t*)(p + 16);
                mma_bf16(s[nt], af, bb);
            }
        }

        float mxlo = -1e30f, mxhi = -1e30f;
#pragma unroll
        for (int nt = 0; nt < 4; nt++) {
            s[nt][0] *= scale; s[nt][1] *= scale; s[nt][2] *= scale; s[nt][3] *= scale;
            mxlo = fmaxf(mxlo, fmaxf(s[nt][0], s[nt][1]));
            mxhi = fmaxf(mxhi, fmaxf(s[nt][2], s[nt][3]));
        }
        mxlo = fmaxf(mxlo, __shfl_xor_sync(0xffffffff, mxlo, 1));
        mxlo = fmaxf(mxlo, __shfl_xor_sync(0xffffffff, mxlo, 2));
        mxhi = fmaxf(mxhi, __shfl_xor_sync(0xffffffff, mxhi, 1));
        mxhi = fmaxf(mxhi, __shfl_xor_sync(0xffffffff, mxhi, 2));
        if ((lane & 3) == 0) { redm[half * 64 + rl] = mxlo; redm[half * 64 + rh] = mxhi; }
        __syncthreads();
        if (t < 64) {
            float mo = m_s[t];
            float mn = fmaxf(mo, fmaxf(redm[t], redm[64 + t]));
            float al = __expf(mo - mn);
            a_s[t] = al; m_s[t] = mn; l_s[t] *= al;
        }
        __syncthreads();

        float mlo = m_s[rl], mhi = m_s[rh], alo = a_s[rl], ahi = a_s[rh];
        float slo = 0.f, shi = 0.f;
        uint32_t afr[2][4];
#pragma unroll
        for (int ks = 0; ks < 2; ks++) {
#pragma unroll
            for (int jj = 0; jj < 2; jj++) {
                int nt = ks * 2 + jj;
                float p0 = __expf(s[nt][0] - mlo), p1 = __expf(s[nt][1] - mlo);
                float p2 = __expf(s[nt][2] - mhi), p3 = __expf(s[nt][3] - mhi);
                slo += p0 + p1; shi += p2 + p3;
                afr[ks][jj * 2 + 0] = packbf(p0, p1);
                afr[ks][jj * 2 + 1] = packbf(p2, p3);
            }
        }
        slo += __shfl_xor_sync(0xffffffff, slo, 1);
        slo += __shfl_xor_sync(0xffffffff, slo, 2);
        shi += __shfl_xor_sync(0xffffffff, shi, 1);
        shi += __shfl_xor_sync(0xffffffff, shi, 2);
        if ((lane & 3) == 0) { reds[half * 64 + rl] = slo; reds[half * 64 + rh] = shi; }

#pragma unroll
        for (int nt = 0; nt < 16; nt++) {
            o[nt][0] *= alo; o[nt][1] *= alo; o[nt][2] *= ahi; o[nt][3] *= ahi;
        }

#pragma unroll
        for (int ks = 0; ks < 2; ks++) {
#pragma unroll
            for (int nb = 0; nb < 8; nb++) {
                uint32_t b4[4];
                ldmT(b4, vsb + (wn2 + ks * 16 + (lane & 15)) * EF_PITCH
                         + nb * 32 + (lane >> 4) * 16);
                mma_bf16(o[2 * nb],     afr[ks], b4);
                mma_bf16(o[2 * nb + 1], afr[ks], b4 + 2);
            }
        }
        __syncthreads();
        if (t < 64) l_s[t] += reds[t] + reds[64 + t];
    }

    __syncthreads();
    if (half == 0) {
#pragma unroll
        for (int nt = 0; nt < 16; nt++) {
            float* plo = Obuf + rl * 132 + nt * 8 + (lane & 3) * 2;
            float* phi = Obuf + rh * 132 + nt * 8 + (lane & 3) * 2;
            plo[0] = o[nt][0]; plo[1] = o[nt][1];
            phi[0] = o[nt][2]; phi[1] = o[nt][3];
        }
    }
    __syncthreads();
    if (half == 1) {
#pragma unroll
        for (int nt = 0; nt < 16; nt++) {
            float* plo = Obuf + rl * 132 + nt * 8 + (lane & 3) * 2;
            float* phi = Obuf + rh * 132 + nt * 8 + (lane & 3) * 2;
            plo[0] += o[nt][0]; plo[1] += o[nt][1];
            phi[0] += o[nt][2]; phi[1] += o[nt][3];
        }
    }
    __syncthreads();
#pragma unroll
    for (int j = 0; j < 16; j++) {
        int id = t + 256 * j;
        int r = id >> 6, cp = id & 63;
        float inv = 1.f / l_s[r];
        float2 v = *(float2*)(Obuf + r * 132 + cp * 2);
        __nv_bfloat162 ob = __float22bfloat162_rn(make_float2(v.x * inv, v.y * inv));
        *(__nv_bfloat162*)(O + base + (size_t)(q0 + r) * 1024 + cp * 2) = ob;
    }
}

// ---------------- main flash (bf16 mma, HD=64, 2 CTA/SM, Obuf aliased) ------
#define MF_PITCH 144
#define MF_QS 0
#define MF_KV0 9216
#define MF_MS  46080
#define MF_LS  46336
#define MF_AS  46592
#define MF_RM  46848
#define MF_RS  47360
#define MF_SMEM 47872

__global__ __launch_bounds__(256, 2) void mflash_kernel(
    const __nv_bfloat16* __restrict__ Q, const __nv_bfloat16* __restrict__ K,
    const __nv_bfloat16* __restrict__ V, __nv_bfloat16* __restrict__ O,
    float scale)
{
    extern __shared__ char sm_[];
    float* Obuf = (float*)(sm_ + MF_KV0);
    float* m_s  = (float*)(sm_ + MF_MS);
    float* l_s  = (float*)(sm_ + MF_LS);
    float* a_s  = (float*)(sm_ + MF_AS);
    float* redm = (float*)(sm_ + MF_RM);
    float* reds = (float*)(sm_ + MF_RS);
    uint32_t smb = smem_u32(sm_);

    int t = threadIdx.x, lane = t & 31, wid = t >> 5;
    int half = wid >> 2, wm = (wid & 3) * 16, wn2 = half * 32;
    int slice = blockIdx.y;
    int sb = slice >> 4, h = slice & 15;
    size_t base = (size_t)sb * Sq * 1024 + (size_t)h * HD1;
    int q0 = blockIdx.x * 64;

#pragma unroll
    for (int j = 0; j < 2; j++) {
        int id = t + 256 * j;
        int r = id >> 3, c = id & 7;
        *(uint4*)(sm_ + MF_QS + r * MF_PITCH + c * 16) =
            *(const uint4*)(Q + base + (size_t)(q0 + r) * 1024 + c * 8);
    }
    if (t < 64) { m_s[t] = -1e30f; l_s[t] = 0.f; }

    {
#pragma unroll
        for (int j = 0; j < 2; j++) {
            int id = t + 256 * j;
            int r = id >> 3, c = id & 7;
            size_t g = base + (size_t)r * 1024 + c * 8;
            cp16(smb + MF_KV0 + r * MF_PITCH + c * 16, K + g);
            cp16(smb + MF_KV0 + 9216 + r * MF_PITCH + c * 16, V + g);
        }
        asm volatile("cp.async.commit_group;");
    }

    float o[8][4];
#pragma unroll
    for (int i = 0; i < 8; i++)
#pragma unroll
        for (int q = 0; q < 4; q++) o[i][q] = 0.f;

    int rl = wm + (lane >> 2), rh = rl + 8;
    int nq = lane >> 2, kr = lane & 3;
    const int NTILE = Sq / 64;

    for (int kt = 0; kt < NTILE; kt++) {
        __syncthreads();
        if (kt + 1 < NTILE) {
            uint32_t stg = smb + MF_KV0 + ((kt + 1) & 1) * 18432;
#pragma unroll
            for (int j = 0; j < 2; j++) {
                int id = t + 256 * j;
                int r = id >> 3, c = id & 7;
                size_t g = base + (size_t)((kt + 1) * 64 + r) * 1024 + c * 8;
                cp16(stg + r * MF_PITCH + c * 16, K + g);
                cp16(stg + 9216 + r * MF_PITCH + c * 16, V + g);
            }
        }
        asm volatile("cp.async.commit_group;");
        asm volatile("cp.async.wait_group 1;");
        __syncthreads();

        uint32_t ksb = smb + MF_KV0 + (kt & 1) * 18432;
        uint32_t vsb = ksb + 9216;
        const char* kcp = sm_ + (ksb - smb);

        float s[4][4];
#pragma unroll
        for (int nt = 0; nt < 4; nt++)
#pragma unroll
            for (int q = 0; q < 4; q++) s[nt][q] = 0.f;
#pragma unroll
        for (int ks = 0; ks < 4; ks++) {
            uint32_t af[4];
            ldmA(af, smb + MF_QS + (wm + (lane & 15)) * MF_PITCH + ks * 32 + (lane >> 4) * 16);
#pragma unroll
            for (int nt = 0; nt < 4; nt++) {
                const char* p = kcp + (wn2 + nt * 8 + nq) * MF_PITCH + ks * 32 + kr * 4;
                uint32_t bb[2];
                bb[0] = *(const uint32_t*)p;
                bb[1] = *(const uint32_t*)(p + 16);
                mma_bf16(s[nt], af, bb);
            }
        }

        float mxlo = -1e30f, mxhi = -1e30f;
#pragma unroll
        for (int nt = 0; nt < 4; nt++) {
            s[nt][0] *= scale; s[nt][1] *= scale; s[nt][2] *= scale; s[nt][3] *= scale;
            mxlo = fmaxf(mxlo, fmaxf(s[nt][0], s[nt][1]));
            mxhi = fmaxf(mxhi, fmaxf(s[nt][2], s[nt][3]));
        }
        mxlo = fmaxf(mxlo, __shfl_xor_sync(0xffffffff, mxlo, 1));
        mxlo = fmaxf(mxlo, __shfl_xor_sync(0xffffffff, mxlo, 2));
        mxhi = fmaxf(mxhi, __shfl_xor_sync(0xffffffff, mxhi, 1));
        mxhi = fmaxf(mxhi, __shfl_xor_sync(0xffffffff, mxhi, 2));
        if ((lane & 3) == 0) { redm[half * 64 + rl] = mxlo; redm[half * 64 + rh] = mxhi; }
        __syncthreads();
        if (t < 64) {
            float mo = m_s[t];
            float mn = fmaxf(mo, fmaxf(redm[t], redm[64 + t]));
            float al = __expf(mo - mn);
            a_s[t] = al; m_s[t] = mn; l_s[t] *= al;
        }
        __syncthreads();

        float mlo = m_s[rl], mhi = m_s[rh], alo = a_s[rl], ahi = a_s[rh];
        float slo = 0.f, shi = 0.f;
        uint32_t afr[2][4];
#pragma unroll
        for (int ks = 0; ks < 2; ks++) {
#pragma unroll
            for (int jj = 0; jj < 2; jj++) {
                int nt = ks * 2 + jj;
                float p0 = __expf(s[nt][0] - mlo), p1 = __expf(s[nt][1] - mlo);
                float p2 = __expf(s[nt][2] - mhi), p3 = __expf(s[nt][3] - mhi);
                slo += p0 + p1; shi += p2 + p3;
                afr[ks][jj * 2 + 0] = packbf(p0, p1);
                afr[ks][jj * 2 + 1] = packbf(p2, p3);
            }
        }
        slo += __shfl_xor_sync(0xffffffff, slo, 1);
        slo += __shfl_xor_sync(0xffffffff, slo, 2);
        shi += __shfl_xor_sync(0xffffffff, shi, 1);
        shi += __shfl_xor_sync(0xffffffff, shi, 2);
        if ((lane & 3) == 0) { reds[half * 64 + rl] = slo; reds[half * 64 + rh] = shi; }

#pragma unroll
        for (int nt = 0; nt < 8; nt++) {
            o[nt][0] *= alo; o[nt][1] *= alo; o[nt][2] *= ahi; o[nt][3] *= ahi;
        }

#pragma unroll
        for (int ks = 0; ks < 2; ks++) {
#pragma unroll
            for (int nb = 0; nb < 4; nb++) {
                uint32_t b4[4];
                ldmT(b4, vsb + (wn2 + ks * 16 + (lane & 15)) * MF_PITCH
                         + nb * 32 + (lane >> 4) * 16);
                mma_bf16(o[2 * nb],     afr[ks], b4);
                mma_bf16(o[2 * nb + 1], afr[ks], b4 + 2);
            }
        }
        __syncthreads();
        if (t < 64) l_s[t] += reds[t] + reds[64 + t];
    }

    __syncthreads();
    if (half == 0) {
#pragma unroll
        for (int nt = 0; nt < 8; nt++) {
            float* plo = Obuf + rl * 68 + nt * 8 + (lane & 3) * 2;
            float* phi = Obuf + rh * 68 + nt * 8 + (lane & 3) * 2;
            plo[0] = o[nt][0]; plo[1] = o[nt][1];
            phi[0] = o[nt][2]; phi[1] = o[nt][3];
        }
    }
    __syncthreads();
    if (half == 1) {
#pragma unroll
        for (int nt = 0; nt < 8; nt++) {
            float* plo = Obuf + rl * 68 + nt * 8 + (lane & 3) * 2;
            float* phi = Obuf + rh * 68 + nt * 8 + (lane & 3) * 2;
            plo[0] += o[nt][0]; plo[1] += o[nt][1];
            phi[0] += o[nt][2]; phi[1] += o[nt][3];
        }
    }
    __syncthreads();
#pragma unroll
    for (int j = 0; j < 8; j++) {
        int id = t + 256 * j;
        int r = id >> 5, cp = id & 31;
        float inv = 1.f / l_s[r];
        float2 v = *(float2*)(Obuf + r * 68 + cp * 2);
        __nv_bfloat162 ob = __float22bfloat162_rn(make_float2(v.x * inv, v.y * inv));
        *(__nv_bfloat162*)(O + base + (size_t)(q0 + r) * 1024 + cp * 2) = ob;
    }
}

// ---------------- fp32 -> bf16 convert (ILP-4, uint4 stores) ----------------
__global__ __launch_bounds__(256) void cvt_kernel(
    const float4* __restrict__ s, uint4* __restrict__ h, int n4)
{
#pragma unroll
    for (int j = 0; j < 4; j++) {
        int i = blockIdx.x * 2048 + j * 512 + threadIdx.x * 2;
        if (i < n4) {
            float4 v0 = s[i], v1 = s[i + 1];
            uint4 hh;
            hh.x = packbf(v0.x, v0.y); hh.y = packbf(v0.z, v0.w);
            hh.z = packbf(v1.x, v1.y); hh.w = packbf(v1.z, v1.w);
            h[i >> 1] = hh;
        }
    }
}

__global__ __launch_bounds__(256) void cvt4_kernel(
    const float4* __restrict__ s0, const float4* __restrict__ s1,
    const float4* __restrict__ s2, const float4* __restrict__ s3,
    uint4* __restrict__ d0, uint4* __restrict__ d1,
    uint4* __restrict__ d2, uint4* __restrict__ d3, int n4)
{
    const float4* s; uint4* d;
    switch (blockIdx.y) {
        case 0:  s = s0; d = d0; break;
        case 1:  s = s1; d = d1; break;
        case 2:  s = s2; d = d2; break;
        default: s = s3; d = d3; break;
    }
#pragma unroll
    for (int j = 0; j < 4; j++) {
        int i = blockIdx.x * 2048 + j * 512 + threadIdx.x * 2;
        if (i < n4) {
            float4 v0 = s[i], v1 = s[i + 1];
            uint4 hh;
            hh.x = packbf(v0.x, v0.y); hh.y = packbf(v0.z, v0.w);
            hh.z = packbf(v1.x, v1.y); hh.w = packbf(v1.z, v1.w);
            d[i >> 1] = hh;
        }
    }
}

// ---------------- zero (ein + stats merged) ----------------
__global__ void zero_ein_kernel() {
    if (blockIdx.x == 0 && threadIdx.x < 32) {
        int t = threadIdx.x;
        if (t < NE) { g_Psum[t] = 0.f; g_fcnt[t] = 0.f; }
        if (t == 0) g_zsum = 0.f;
    }
    size_t n = EINSZ / 8;
    uint4 z = make_uint4(0, 0, 0, 0);
    uint4* ph = (uint4*)g_einh;
    for (size_t i = blockIdx.x * (size_t)blockDim.x + threadIdx.x; i < n;
         i += (size_t)gridDim.x * blockDim.x) ph[i] = z;
}

// ---------------- block reduce ----------------
__device__ __forceinline__ void block_reduce2(float& s, float& s2) {
    __shared__ float rs[8], rs2[8];
#pragma unroll
    for (int o = 16; o > 0; o >>= 1) {
        s  += __shfl_xor_sync(0xffffffff, s, o);
        s2 += __shfl_xor_sync(0xffffffff, s2, o);
    }
    int lane = threadIdx.x & 31, w = threadIdx.x >> 5;
    if (lane == 0) { rs[w] = s; rs2[w] = s2; }
    __syncthreads();
    float ts = 0.f, ts2 = 0.f;
#pragma unroll
    for (int i = 0; i < 8; i++) { ts += rs[i]; ts2 += rs2[i]; }
    s = ts; s2 = ts2;
}

// ---------------- LN1 + gate (fused; attn in bf16) ----------------
__global__ __launch_bounds__(256) void ln1gate_kernel(
    const float* __restrict__ x, const float* __restrict__ g,
    const float* __restrict__ b, const float* __restrict__ gateW)
{
    __shared__ float ga[8][NE];
    size_t tok = blockIdx.x;
    int t = threadIdx.x, lane = t & 31, w = t >> 5;
    float v[4], s = 0.f, s2 = 0.f;
#pragma unroll
    for (int u = 0; u < 4; u++) {
        int j = t + u * 256;
        float val = x[tok * Dm + j] + __bfloat162float(g_attnb[tok * Dm + j]);
        v[u] = val; s += val; s2 += val * val;
    }
    block_reduce2(s, s2);
    float mean = s * (1.f / Dm);
    float var  = s2 * (1.f / Dm) - mean * mean;
    float inv  = rsqrtf(var + 1e-5f);

    float acc[NE];
#pragma unroll
    for (int e = 0; e < NE; e++) acc[e] = 0.f;
#pragma unroll
    for (int u = 0; u < 4; u++) {
        int j = t + u * 256;
        float x1v = (v[u] - mean) * inv * g[j] + b[j];
        g_x1[tok * Dm + j] = x1v;
        const float* wr = gateW + (size_t)j * NE;
#pragma unroll
        for (int e = 0; e < NE; e++) acc[e] += x1v * wr[e];
    }
#pragma unroll
    for (int e = 0; e < NE; e++)
#pragma unroll
        for (int o = 16; o > 0; o >>= 1)
            acc[e] += __shfl_xor_sync(0xffffffff, acc[e], o);
    if (lane == 0)
#pragma unroll
        for (int e = 0; e < NE; e++) ga[w][e] = acc[e];
    __syncthreads();

    if (t == 0) {
        float lg[NE];
#pragma unroll
        for (int e = 0; e < NE; e++) {
            float sv = 0.f;
#pragma unroll
            for (int i = 0; i < 8; i++) sv += ga[i][e];
            lg[e] = sv;
        }
        float mx = lg[0];
#pragma unroll
        for (int e = 1; e < NE; e++) mx = fmaxf(mx, lg[e]);
        float p[NE], se = 0.f;
#pragma unroll
        for (int e = 0; e < NE; e++) { p[e] = __expf(lg[e] - mx); se += p[e]; }
        float invs = 1.f / se;
        float lse = mx + logf(se);
        atomicAdd(&g_zsum, lse * lse);
        int i0 = 0, i1 = -1;
        float b0 = -1.f, b1 = -1.f;
#pragma unroll
        for (int e = 0; e < NE; e++) {
            float pe = p[e] * invs;
            atomicAdd(&g_Psum[e], pe);
            if (pe > b0) { b1 = b0; i1 = i0; b0 = pe; i0 = e; }
            else if (pe > b1) { b1 = pe; i1 = e; }
        }
        atomicAdd(&g_fcnt[i0], 1.f);
        g_i0[tok] = i0; g_i1[tok] = i1;
        g_g0[tok] = b0; g_g1[tok] = b1;
    }
}

// ---------------- routing positions ----------------
__global__ __launch_bounds__(256) void pos_kernel() {
    int warp = threadIdx.x >> 5, lane = threadIdx.x & 31;
    if (warp >= Bt) return;
    int b = warp;
    unsigned lt = (1u << lane) - 1u;
    int cnt[NE];
#pragma unroll
    for (int e = 0; e < NE; e++) cnt[e] = 0;

    for (int ch = 0; ch < Sq / 32; ch++) {
        int tok = b * Sq + ch * 32 + lane;
        int e0 = g_i0[tok];
        int myp = 0;
#pragma unroll
        for (int e = 0; e < NE; e++) {
            unsigned m = __ballot_sync(0xffffffff, e0 == e);
            if (e0 == e) myp = cnt[e] + __popc(m & lt);
            cnt[e] += __popc(m);
        }
        g_k0[tok] = (myp < CAP) ? 1 : 0;
        g_p0[tok] = min(myp, CAP - 1);
    }
    for (int ch = 0; ch < Sq / 32; ch++) {
        int tok = b * Sq + ch * 32 + lane;
        int e1 = g_i1[tok];
        bool valid = g_g1[tok] > 0.2f;
        int myp = 0;
#pragma unroll
        for (int e = 0; e < NE; e++) {
            unsigned m = __ballot_sync(0xffffffff, valid && (e1 == e));
            if (valid && (e1 == e)) myp = cnt[e] + __popc(m & lt);
            cnt[e] += __popc(m);
        }
        bool keep = valid && (myp < CAP);
        g_k1[tok] = keep ? 1 : 0;
        g_p1[tok] = valid ? min(myp, CAP - 1) : 0;
    }
}

// ---------------- scatter (x1 fp32 -> einh bf16) ----------------
__global__ __launch_bounds__(256) void scatter_kernel() {
    int idx = blockIdx.x;
    int tok = idx >> 1, slot = idx & 1;
    int keep = slot ? g_k1[tok] : g_k0[tok];
    if (!keep) return;
    int e = slot ? g_i1[tok] : g_i0[tok];
    int p = slot ? g_p1[tok] : g_p0[tok];
    int b = tok / Sq;
    const float4* src = (const float4*)(g_x1 + (size_t)tok * Dm);
    size_t ro = (((size_t)e * Bt + b) * CAP + p) * Dm;
    uint2* dh = (uint2*)(g_einh + ro);
    float4 v = src[threadIdx.x];
    uint2 hh;
    hh.x = packbf(v.x, v.y);
    hh.y = packbf(v.z, v.w);
    dh[threadIdx.x] = hh;
}

// ---------------- combine + LN2 ----------------
__global__ __launch_bounds__(256) void combine_ln_kernel(
    const float* __restrict__ g2, const float* __restrict__ b2,
    float* __restrict__ out)
{
    size_t tok = blockIdx.x;
    int t = threadIdx.x;
    int b = (int)(tok >> 10);
    float w0 = g_k0[tok] ? g_g0[tok] : 0.f;
    float w1 = g_k1[tok] ? g_g1[tok] : 0.f;
    const __nv_bfloat16* r0 = g_eoutb + (((size_t)g_i0[tok] * Bt + b) * CAP + g_p0[tok]) * Dm;
    const __nv_bfloat16* r1 = g_eoutb + (((size_t)g_i1[tok] * Bt + b) * CAP + g_p1[tok]) * Dm;

    float v[4], s = 0.f, s2 = 0.f;
#pragma unroll
    for (int u = 0; u < 4; u++) {
        int j = t + u * 256;
        float val = g_x1[tok * Dm + j]
                  + w0 * __bfloat162float(r0[j]) + w1 * __bfloat162float(r1[j]);
        v[u] = val; s += val; s2 += val * val;
    }
    block_reduce2(s, s2);
    float mean = s * (1.f / Dm);
    float var  = s2 * (1.f / Dm) - mean * mean;
    float inv  = rsqrtf(var + 1e-5f);
#pragma unroll
    for (int u = 0; u < 4; u++) {
        int j = t + u * 256;
        out[tok * Dm + j] = (v[u] - mean) * inv * g2[j] + b2[j];
    }
}

// ---------------- finalize aux ----------------
__global__ void finalize_kernel(float* __restrict__ out) {
    if (threadIdx.x == 0 && blockIdx.x == 0) {
        float invN = 1.f / (float)NT;
        float sfp = 0.f;
#pragma unroll
        for (int e = 0; e < NE; e++)
            sfp += (g_fcnt[e] * invN) * (g_Psum[e] * invN);
        float bal = 0.01f * (float)NE * sfp;
        float zl  = 0.001f * g_zsum * invN;
        out[NTD + 0] = bal + zl;
        out[NTD + 1] = bal;
        out[NTD + 2] = zl;
    }
}

// ---------------- host launcher ----------------
extern "C" void kernel_launch(void* const* d_in, const int* in_sizes, int n_in,
                              void* d_out, int out_size)
{
    const float* x      = (const float*)d_in[0];
    const float* Wq     = (const float*)d_in[1];
    const float* Wk     = (const float*)d_in[2];
    const float* Wv     = (const float*)d_in[3];
    const float* Wo     = (const float*)d_in[4];
    const float* bq     = (const float*)d_in[5];
    const float* bk     = (const float*)d_in[6];
    const float* bv     = (const float*)d_in[7];
    const float* bo     = (const float*)d_in[8];
    const float* ln1_g  = (const float*)d_in[9];
    const float* ln1_b  = (const float*)d_in[10];
    const float* ln2_g  = (const float*)d_in[11];
    const float* ln2_b  = (const float*)d_in[12];
    const float* gate_W = (const float*)d_in[13];
    const float* eWq    = (const float*)d_in[14];
    const float* eWk    = (const float*)d_in[15];
    const float* eWv    = (const float*)d_in[16];
    const float* eWo    = (const float*)d_in[17];
    float* out = (float*)d_out;

    void *pattnb, *px1, *peoutb, *pxh, *pqkvh, *poh;
    void *peinh, *peqkv, *peoh;
    void *pwqkvh, *pwoh, *pewh, *pewoh, *pbqkv;
    cudaGetSymbolAddress(&pattnb, g_attnb); cudaGetSymbolAddress(&px1, g_x1);
    cudaGetSymbolAddress(&peoutb, g_eoutb); cudaGetSymbolAddress(&pxh, g_xh);
    cudaGetSymbolAddress(&pqkvh, g_qkvh);   cudaGetSymbolAddress(&poh, g_oh);
    cudaGetSymbolAddress(&peinh, g_einh);   cudaGetSymbolAddress(&peqkv, g_eqkv);
    cudaGetSymbolAddress(&peoh, g_eoh);
    cudaGetSymbolAddress(&pwqkvh, g_wqkvh); cudaGetSymbolAddress(&pwoh, g_woh);
    cudaGetSymbolAddress(&pewh, g_ewh);     cudaGetSymbolAddress(&pewoh, g_ewoh);
    cudaGetSymbolAddress(&pbqkv, g_bqkv);

    cudaFuncSetAttribute(gemm_mma_kernel<0>, cudaFuncAttributeMaxDynamicSharedMemorySize, GEMM_SMEM);
    cudaFuncSetAttribute(gemm_mma_kernel<1>, cudaFuncAttributeMaxDynamicSharedMemorySize, GEMM_SMEM);
    cudaFuncSetAttribute(mflash_kernel, cudaFuncAttributeMaxDynamicSharedMemorySize, MF_SMEM);
    cudaFuncSetAttribute(eflash_kernel, cudaFuncAttributeMaxDynamicSharedMemorySize, EF_SMEM);

    zero_ein_kernel<<<2048, 256>>>();

    cudaMemcpyAsync((float*)pbqkv,          bq, Dm * sizeof(float), cudaMemcpyDeviceToDevice);
    cudaMemcpyAsync((float*)pbqkv + Dm,     bk, Dm * sizeof(float), cudaMemcpyDeviceToDevice);
    cudaMemcpyAsync((float*)pbqkv + 2 * Dm, bv, Dm * sizeof(float), cudaMemcpyDeviceToDevice);

    __nv_bfloat16* wqkv = (__nv_bfloat16*)pwqkvh;
    __nv_bfloat16* ewh  = (__nv_bfloat16*)pewh;
    const int WB1 = (int)(DMDM / 4);
    cvt4_kernel<<<dim3((WB1 + 2047) / 2048, 4), 256>>>(
        (const float4*)Wq, (const float4*)Wk, (const float4*)Wv, (const float4*)Wo,
        (uint4*)wqkv, (uint4*)(wqkv + DMDM), (uint4*)(wqkv + 2 * DMDM), (uint4*)pwoh, WB1);
    const int WBE = (int)(NE * DMDM / 4);
    cvt4_kernel<<<dim3((WBE + 2047) / 2048, 4), 256>>>(
        (const float4*)eWq, (const float4*)eWk, (const float4*)eWv, (const float4*)eWo,
        (uint4*)ewh, (uint4*)(ewh + NE * DMDM), (uint4*)(ewh + 2 * NE * DMDM), (uint4*)pewoh, WBE);

    cvt_kernel<<<(int)(NTD / 4 / 2048), 256>>>((const float4*)x, (uint4*)pxh, (int)(NTD / 4));

    // main QKV: one batched launch, z in [0,3)
    gemm_mma_kernel<1><<<dim3(Dm / 128, NT / 128, 3), 256, GEMM_SMEM>>>(
        (__nv_bfloat16*)pxh, wqkv, (const float*)pbqkv, pqkvh,
        NT, Dm, Dm, 0, DMDM, NTD, Dm, 3);

    __nv_bfloat16* qkv = (__nv_bfloat16*)pqkvh;
    mflash_kernel<<<dim3(Sq / 64, Bt * NH), 256, MF_SMEM>>>(
        qkv, qkv + NTD, qkv + 2 * NTD, (__nv_bfloat16*)poh, 0.125f);

    // Wo: bf16 out
    gemm_mma_kernel<1><<<dim3(Dm / 128, NT / 128, 1), 256, GEMM_SMEM>>>(
        (__nv_bfloat16*)poh, (__nv_bfloat16*)pwoh, bo, pattnb,
        NT, Dm, Dm, 0, 0, 0, 0, 1);

    ln1gate_kernel<<<NT, 256>>>(x, ln1_g, ln1_b, gate_W);
    pos_kernel<<<1, 256>>>();
    scatter_kernel<<<NT * 2, 256>>>();

    size_t sA = (size_t)EROWS * Dm;
    gemm_mma_kernel<1><<<dim3(Dm / 128, EROWS / 128, 24), 256, GEMM_SMEM>>>(
        (__nv_bfloat16*)peinh, ewh, nullptr, peqkv,
        EROWS, Dm, Dm, sA, DMDM, sA, 0, NE);

    __nv_bfloat16* eqkv = (__nv_bfloat16*)peqkv;
    eflash_kernel<<<dim3(CAP / 64, NE * Bt * NHM), 256, EF_SMEM>>>(
        eqkv, eqkv + EINSZ, eqkv + 2 * EINSZ, (__nv_bfloat16*)peoh, 0.0883883476483184f);

    gemm_mma_kernel<1><<<dim3(Dm / 128, EROWS / 128, NE), 256, GEMM_SMEM>>>(
        (__nv_bfloat16*)peoh, (__nv_bfloat16*)pewoh, nullptr, peoutb,
        EROWS, Dm, Dm, sA, DMDM, sA, 0, NE);

    combine_ln_kernel<<<NT, 256>>>(ln2_g, ln2_b, out);
    finalize_kernel<<<1, 32>>>(out);
}